// round 16
// baseline (speedup 1.0000x reference)
#include <cuda_runtime.h>
#include <cuda_fp16.h>
#include <cstdint>

#define T_SEQ 2048
#define D_MODEL 1024
#define BT_ROWS 4096            // B*T

// ---------------------------------------------------------------------------
// Scratch (device globals; no allocations anywhere).
// ---------------------------------------------------------------------------
__device__ __half g_qkv_hi[(size_t)BT_ROWS * 3072];
__device__ __half g_att_hi[(size_t)BT_ROWS * 1024];
__device__ __half g_xa_hi[(size_t)BT_ROWS * 1024];
__device__ __half g_wa_hi[(size_t)3072 * 1024];  // w_attn^T [N,K]
__device__ __half g_wp_hi[(size_t)1024 * 1024];  // w_proj^T [N,K]
__device__ __half g_wp_lo[(size_t)1024 * 1024];

// ---------------------------------------------------------------------------
// Helpers (plain sm_80-era PTX only)
// ---------------------------------------------------------------------------
__device__ __forceinline__ uint32_t smem_u32(const void* p) {
    uint32_t a;
    asm("{ .reg .u64 t; cvta.to.shared.u64 t, %1; cvt.u32.u64 %0, t; }"
        : "=r"(a) : "l"(p));
    return a;
}

__device__ __forceinline__ void cpa16(uint32_t s, const void* g) {
    asm volatile("cp.async.cg.shared.global [%0], [%1], 16;" :: "r"(s), "l"(g));
}

__device__ __forceinline__ void ldsm4(uint32_t* r, uint32_t a) {
    asm volatile("ldmatrix.sync.aligned.m8n8.x4.shared.b16 {%0,%1,%2,%3}, [%4];"
                 : "=r"(r[0]), "=r"(r[1]), "=r"(r[2]), "=r"(r[3]) : "r"(a));
}

__device__ __forceinline__ void ldsm4t(uint32_t* r, uint32_t a) {
    asm volatile("ldmatrix.sync.aligned.m8n8.x4.trans.shared.b16 {%0,%1,%2,%3}, [%4];"
                 : "=r"(r[0]), "=r"(r[1]), "=r"(r[2]), "=r"(r[3]) : "r"(a));
}

// f16 x f16 -> f32 accumulate
__device__ __forceinline__ void mma_f32(float* d, const uint32_t* a,
                                        const uint32_t* b) {
    asm volatile(
        "mma.sync.aligned.m16n8k16.row.col.f32.f16.f16.f32 "
        "{%0,%1,%2,%3}, {%4,%5,%6,%7}, {%8,%9}, {%0,%1,%2,%3};"
        : "+f"(d[0]), "+f"(d[1]), "+f"(d[2]), "+f"(d[3])
        : "r"(a[0]), "r"(a[1]), "r"(a[2]), "r"(a[3]), "r"(b[0]), "r"(b[1]));
}

// f16 x f16 -> f16 accumulate (GEMM lo cross-term)
__device__ __forceinline__ void mma_f16(uint32_t* d, const uint32_t* a,
                                        const uint32_t* b) {
    asm volatile(
        "mma.sync.aligned.m16n8k16.row.col.f16.f16.f16.f16 "
        "{%0,%1}, {%2,%3,%4,%5}, {%6,%7}, {%0,%1};"
        : "+r"(d[0]), "+r"(d[1])
        : "r"(a[0]), "r"(a[1]), "r"(a[2]), "r"(a[3]), "r"(b[0]), "r"(b[1]));
}

// pack a pair of fp32 -> f16x2 (single rounding)
__device__ __forceinline__ uint32_t pack2(float a, float b) {
    __half2 h;
    h.x = __float2half(a);
    h.y = __float2half(b);
    return *(uint32_t*)&h;
}

// ---------------------------------------------------------------------------
// Fused preparation kernel (identical to R15).
// ---------------------------------------------------------------------------
#define PREP_X_BLOCKS    (BT_ROWS * D_MODEL / 4 / 256)   // 4096
#define PREP_WA_BLOCKS   ((3072 / 32) * (1024 / 32))     // 3072
#define PREP_WP_BLOCKS   ((1024 / 32) * (1024 / 32))     // 1024
#define PREP_BLOCKS      (PREP_X_BLOCKS + PREP_WA_BLOCKS + PREP_WP_BLOCKS)

__global__ __launch_bounds__(256) void prep_all(
    const float* __restrict__ x,      __half* __restrict__ xa,
    const float* __restrict__ wa,     __half* __restrict__ wah,
    const float* __restrict__ wp,     __half* __restrict__ wph,
    __half* __restrict__ wpl)
{
    __shared__ float t[32][33];
    const int bid = blockIdx.x, tid = threadIdx.x;

    if (bid < PREP_X_BLOCKS) {
        int i = (bid * 256 + tid) * 4;
        float4 v = *(const float4*)(x + i);
        ((uint32_t*)(xa + i))[0] = pack2(v.x, v.y);
        ((uint32_t*)(xa + i))[1] = pack2(v.z, v.w);
        return;
    }

    const int tx = tid & 31, ty = tid >> 5;

    if (bid < PREP_X_BLOCKS + PREP_WA_BLOCKS) {
        const int bb = bid - PREP_X_BLOCKS;
        const int n0 = (bb % (3072 / 32)) * 32;
        const int k0 = (bb / (3072 / 32)) * 32;
#pragma unroll
        for (int j = 0; j < 32; j += 8)
            t[ty + j][tx] = wa[(size_t)(k0 + ty + j) * 3072 + n0 + tx];
        __syncthreads();
#pragma unroll
        for (int j = 0; j < 32; j += 8)
            wah[(size_t)(n0 + ty + j) * 1024 + k0 + tx] =
                __float2half(t[tx][ty + j]);
        return;
    }

    {
        const int bb = bid - PREP_X_BLOCKS - PREP_WA_BLOCKS;
        const int n0 = (bb % (1024 / 32)) * 32;
        const int k0 = (bb / (1024 / 32)) * 32;
#pragma unroll
        for (int j = 0; j < 32; j += 8)
            t[ty + j][tx] = wp[(size_t)(k0 + ty + j) * 1024 + n0 + tx];
        __syncthreads();
#pragma unroll
        for (int j = 0; j < 32; j += 8) {
            float v = t[tx][ty + j];
            __half h = __float2half(v);
            size_t o = (size_t)(n0 + ty + j) * 1024 + k0 + tx;
            wph[o] = h;
            wpl[o] = __float2half(v - __half2float(h));
        }
    }
}

// ---------------------------------------------------------------------------
// HMMA GEMM: C = Ah @ (Bh [+ Bl])^T + bias   (identical to R15)
// ---------------------------------------------------------------------------
#define GBK 32
#define ROWB 80
#define TILE_B (128 * ROWB)

template <int TERMS, int CVT_OUT, int NWARP>
__global__ __launch_bounds__(NWARP * 32) void gemm_hmma(
    const __half* __restrict__ Ahi,
    const __half* __restrict__ Bhi, const __half* __restrict__ Blo,
    const float* __restrict__ bias, float* __restrict__ C,
    __half* __restrict__ Chi,
    int N, int K)
{
    constexpr uint32_t STAGE = (1 + TERMS) * TILE_B;
    constexpr int NT = NWARP * 32;
    constexpr int MI = (NWARP == 4) ? 4 : 2;

    extern __shared__ char smc[];
    const uint32_t sb = smem_u32(smc);
    const int tid = threadIdx.x, lane = tid & 31, wid = tid >> 5;
    const int bm = blockIdx.y * 128, bn = blockIdx.x * 128;
    const int mbw = (NWARP == 4) ? (wid & 1) * 64 : (wid & 3) * 32;
    const int nbw = (NWARP == 4) ? (wid >> 1) * 64 : (wid >> 2) * 64;

    float acc[MI][8][4];
    uint32_t accL[MI][8][2];
#pragma unroll
    for (int m = 0; m < MI; m++)
#pragma unroll
        for (int n = 0; n < 8; n++) {
#pragma unroll
            for (int j = 0; j < 4; j++) acc[m][n][j] = 0.f;
            accL[m][n][0] = 0u; accL[m][n][1] = 0u;
        }

    const uint32_t aoff =
        (uint32_t)(mbw + (lane & 15)) * ROWB + (uint32_t)(lane >> 4) * 16;
    const uint32_t boff =
        (uint32_t)(nbw + (lane >> 4) * 8 + (lane & 7)) * ROWB +
        (uint32_t)((lane >> 3) & 1) * 16;

    auto load_stage = [&](int s, int kt) {
        const uint32_t st = sb + s * STAGE;
        const int kc = kt * GBK;
        const __half* gp[3] = {Ahi, Bhi, Blo};
#pragma unroll
        for (int c = 0; c < (1 + TERMS) * 512 / NT; c++) {
            int idx = tid + c * NT;
            int tile = idx >> 9;
            int rem = idx & 511;
            int row = rem >> 2, q = rem & 3;
            const int rbase = (tile == 0) ? bm : bn;
            const __half* g =
                gp[tile] + (size_t)(rbase + row) * K + kc + q * 8;
            cpa16(st + tile * TILE_B + row * ROWB + q * 16, g);
        }
        asm volatile("cp.async.commit_group;" ::: "memory");
    };

    const int KT = K / GBK;
    load_stage(0, 0);
    load_stage(1, 1);

    for (int kt = 0; kt < KT; kt++) {
        const int s = kt % 3;
        if (kt + 1 < KT)
            asm volatile("cp.async.wait_group 1;" ::: "memory");
        else
            asm volatile("cp.async.wait_group 0;" ::: "memory");
        __syncthreads();

        if (kt + 2 < KT) load_stage((kt + 2) % 3, kt + 2);

        const uint32_t st = sb + s * STAGE;
        const uint32_t stAh = st;
        const uint32_t stBh = st + TILE_B, stBl = st + 2 * TILE_B;

#pragma unroll
        for (int ks = 0; ks < 2; ks++) {
            const uint32_t ko = ks * 32;
            uint32_t bh[4][4], ah[MI][4];
#pragma unroll
            for (int p = 0; p < 4; p++)
                ldsm4(bh[p], stBh + boff + p * 16 * ROWB + ko);
#pragma unroll
            for (int m = 0; m < MI; m++)
                ldsm4(ah[m], stAh + aoff + m * 16 * ROWB + ko);
#pragma unroll
            for (int n = 0; n < 8; n++)
#pragma unroll
                for (int m = 0; m < MI; m++)
                    mma_f32(acc[m][n], ah[m], &bh[n >> 1][(n & 1) * 2]);
            if (TERMS == 2) {
                uint32_t bl[4][4];
#pragma unroll
                for (int p = 0; p < 4; p++)
                    ldsm4(bl[p], stBl + boff + p * 16 * ROWB + ko);
#pragma unroll
                for (int n = 0; n < 8; n++)
#pragma unroll
                    for (int m = 0; m < MI; m++)
                        mma_f16(accL[m][n], ah[m], &bl[n >> 1][(n & 1) * 2]);
            }
        }
    }

    // Epilogue
    const int rql = lane >> 2, cql = (lane & 3) * 2;
#pragma unroll
    for (int m = 0; m < MI; m++) {
        const int row = bm + mbw + m * 16 + rql;
#pragma unroll
        for (int n = 0; n < 8; n++) {
            const int col = bn + nbw + n * 8 + cql;
            const float bx = bias[col], by = bias[col + 1];
            float v0 = acc[m][n][0] + bx;
            float v1 = acc[m][n][1] + by;
            float v2 = acc[m][n][2] + bx;
            float v3 = acc[m][n][3] + by;
            if (TERMS == 2) {
                __half2 lo0 = *(__half2*)&accL[m][n][0];
                __half2 lo1 = *(__half2*)&accL[m][n][1];
                v0 += __half2float(lo0.x);
                v1 += __half2float(lo0.y);
                v2 += __half2float(lo1.x);
                v3 += __half2float(lo1.y);
            }
            if (CVT_OUT) {
                *(uint32_t*)(Chi + (size_t)row * N + col) = pack2(v0, v1);
                *(uint32_t*)(Chi + (size_t)(row + 8) * N + col) = pack2(v2, v3);
            } else {
                *(float2*)(C + (size_t)row * N + col) = make_float2(v0, v1);
                *(float2*)(C + (size_t)(row + 8) * N + col) = make_float2(v2, v3);
            }
        }
    }
}

// ---------------------------------------------------------------------------
// HMMA flash attention, KV tile = 128 (halved iteration count):
//   S = Qh*Kh ;  O += P16 * Vh   (f32 accum)
// 3-stage early-issue pipeline, hoisted Q fragments.
// Smem: Q 18432 + 3 x (2*18432 + 512) = 130560.
// ---------------------------------------------------------------------------
#define AROW 144
#define ATT_QBYTES (128 * AROW)           // 18432
#define AKV (128 * AROW)                  // 18432 (128-row KV tile)
#define ATT_STAGE (2 * AKV + 512)         // 37376
#define ATT_SMEM (ATT_QBYTES + 3 * ATT_STAGE)   // 130560

__global__ __launch_bounds__(256) void attn_hmma(
    const __half* __restrict__ qkv_hi,
    const float* __restrict__ mask,
    __half* __restrict__ out_hi)
{
    extern __shared__ char smc[];
    const uint32_t sb = smem_u32(smc);
    const int tid = threadIdx.x, lane = tid & 31, w = tid >> 5;
    const int qt = blockIdx.x * 128;
    const int h = blockIdx.y, b = blockIdx.z;

    // ---- Q load (hi only), committed with kv0 ----
#pragma unroll
    for (int i = 0; i < 4; i++) {
        int idx = tid + i * 256;
        int row = idx >> 3, c = idx & 7;
        const __half* g = qkv_hi +
            (size_t)(b * T_SEQ + qt + row) * 3072 + h * 64 + c * 8;
        cpa16(sb + row * AROW + c * 16, g);
    }

    const uint32_t stg0 = sb + ATT_QBYTES;

    auto load_kv = [&](int s, int kt) {
        const uint32_t st = stg0 + s * ATT_STAGE;
        // 2 tiles (K, V) x 128 rows x 8 chunks = 2048 chunks, 8 per thread
#pragma unroll
        for (int i = 0; i < 8; i++) {
            int idx = tid + i * 256;
            int tile = idx >> 10;
            int rem = idx & 1023;
            int row = rem >> 3, c = rem & 7;
            int coff = ((tile == 0) ? 1024 : 2048) + h * 64;
            const __half* g = qkv_hi +
                (size_t)(b * T_SEQ + kt * 128 + row) * 3072 + coff + c * 8;
            cpa16(st + tile * AKV + row * AROW + c * 16, g);
        }
        if (tid < 32)
            cpa16(st + 2 * AKV + tid * 16,
                  mask + (size_t)b * T_SEQ + kt * 128 + tid * 4);
        asm volatile("cp.async.commit_group;" ::: "memory");
    };

    load_kv(0, 0);    // group: Q + kv0
    load_kv(1, 1);    // group: kv1

    const uint32_t aoffQ = (uint32_t)(w * 16 + (lane & 15)) * AROW +
                           (uint32_t)(lane >> 4) * 16;
    const uint32_t boffK = (uint32_t)((lane >> 4) * 8 + (lane & 7)) * AROW +
                           (uint32_t)((lane >> 3) & 1) * 16;
    const uint32_t voffV = (uint32_t)(lane & 15) * AROW +
                           (uint32_t)(lane >> 4) * 16;

    uint32_t qf[4][4];
    float mst0 = -1e30f, mst1 = -1e30f, lst0 = 0.f, lst1 = 0.f;
    float O[8][4];
#pragma unroll
    for (int n = 0; n < 8; n++)
#pragma unroll
        for (int j = 0; j < 4; j++) O[n][j] = 0.f;

    const int NKV = T_SEQ / 128;    // 16
    for (int kt = 0; kt < NKV; kt++) {
        const int s = kt % 3;
        if (kt + 1 < NKV)
            asm volatile("cp.async.wait_group 1;" ::: "memory");
        else
            asm volatile("cp.async.wait_group 0;" ::: "memory");
        __syncthreads();

        if (kt == 0) {
#pragma unroll
            for (int kg = 0; kg < 4; kg++)
                ldsm4(qf[kg], sb + aoffQ + kg * 32);
        }
        if (kt + 2 < NKV) load_kv((kt + 2) % 3, kt + 2);

        const uint32_t st = stg0 + s * ATT_STAGE;
        const float* mskp = (const float*)(smc + ATT_QBYTES +
                                           s * ATT_STAGE + 2 * AKV);

        // ---- S = Qh*Kh over 128 kv rows (16 n8 blocks) ----
        float S[16][4];
#pragma unroll
        for (int n = 0; n < 16; n++)
#pragma unroll
            for (int j = 0; j < 4; j++) S[n][j] = 0.f;

#pragma unroll
        for (int kg = 0; kg < 4; kg++) {
#pragma unroll
            for (int nb = 0; nb < 8; nb++) {
                uint32_t kh[4];
                ldsm4(kh, st + boffK + nb * 16 * AROW + kg * 32);
                mma_f32(S[2 * nb],     qf[kg], &kh[0]);
                mma_f32(S[2 * nb + 1], qf[kg], &kh[2]);
            }
        }

        // ---- scale + double mask + online softmax ----
        float mx0 = -1e30f, mx1 = -1e30f;
#pragma unroll
        for (int n = 0; n < 16; n++) {
            float2 mk = *(const float2*)(mskp + n * 8 + (lane & 3) * 2);
            float m0 = 2.f * mk.x, m1 = 2.f * mk.y;
            S[n][0] = fmaf(S[n][0], 0.125f, m0);
            S[n][1] = fmaf(S[n][1], 0.125f, m1);
            S[n][2] = fmaf(S[n][2], 0.125f, m0);
            S[n][3] = fmaf(S[n][3], 0.125f, m1);
            mx0 = fmaxf(mx0, fmaxf(S[n][0], S[n][1]));
            mx1 = fmaxf(mx1, fmaxf(S[n][2], S[n][3]));
        }
        mx0 = fmaxf(mx0, __shfl_xor_sync(0xffffffffu, mx0, 1));
        mx0 = fmaxf(mx0, __shfl_xor_sync(0xffffffffu, mx0, 2));
        mx1 = fmaxf(mx1, __shfl_xor_sync(0xffffffffu, mx1, 1));
        mx1 = fmaxf(mx1, __shfl_xor_sync(0xffffffffu, mx1, 2));

        const float mn0 = fmaxf(mst0, mx0), mn1 = fmaxf(mst1, mx1);
        const float cr0 = __expf(mst0 - mn0), cr1 = __expf(mst1 - mn1);
        mst0 = mn0; mst1 = mn1;

        float rs0 = 0.f, rs1 = 0.f;
#pragma unroll
        for (int n = 0; n < 16; n++) {
            S[n][0] = __expf(S[n][0] - mn0);
            S[n][1] = __expf(S[n][1] - mn0);
            S[n][2] = __expf(S[n][2] - mn1);
            S[n][3] = __expf(S[n][3] - mn1);
            rs0 += S[n][0] + S[n][1];
            rs1 += S[n][2] + S[n][3];
        }
        rs0 += __shfl_xor_sync(0xffffffffu, rs0, 1);
        rs0 += __shfl_xor_sync(0xffffffffu, rs0, 2);
        rs1 += __shfl_xor_sync(0xffffffffu, rs1, 1);
        rs1 += __shfl_xor_sync(0xffffffffu, rs1, 2);
        lst0 = lst0 * cr0 + rs0;
        lst1 = lst1 * cr1 + rs1;

#pragma unroll
        for (int n = 0; n < 8; n++) {
            O[n][0] *= cr0; O[n][1] *= cr0;
            O[n][2] *= cr1; O[n][3] *= cr1;
        }

        // ---- O += P16 * Vh (128-deep k this tile) ----
#pragma unroll
        for (int kg = 0; kg < 8; kg++) {
            uint32_t ph[4];
            ph[0] = pack2(S[2 * kg][0],     S[2 * kg][1]);
            ph[1] = pack2(S[2 * kg][2],     S[2 * kg][3]);
            ph[2] = pack2(S[2 * kg + 1][0], S[2 * kg + 1][1]);
            ph[3] = pack2(S[2 * kg + 1][2], S[2 * kg + 1][3]);
#pragma unroll
            for (int nb = 0; nb < 4; nb++) {
                uint32_t vh[4];
                ldsm4t(vh, st + AKV + voffV + kg * 16 * AROW + nb * 32);
                mma_f32(O[2 * nb],     ph, &vh[0]);
                mma_f32(O[2 * nb + 1], ph, &vh[2]);
            }
        }
    }

    const float inv0 = 1.f / lst0, inv1 = 1.f / lst1;
    const int row0 = b * T_SEQ + qt + w * 16 + (lane >> 2);
    const int colb = h * 64 + (lane & 3) * 2;
#pragma unroll
    for (int n = 0; n < 8; n++) {
        const size_t o0 = (size_t)row0 * D_MODEL + colb + n * 8;
        const size_t o1 = (size_t)(row0 + 8) * D_MODEL + colb + n * 8;
        *(uint32_t*)(out_hi + o0) = pack2(O[n][0] * inv0, O[n][1] * inv0);
        *(uint32_t*)(out_hi + o1) = pack2(O[n][2] * inv1, O[n][3] * inv1);
    }
}

// ---------------------------------------------------------------------------
extern "C" void kernel_launch(void* const* d_in, const int* in_sizes, int n_in,
                              void* d_out, int out_size)
{
    const float* x      = (const float*)d_in[0];
    const float* mask   = (const float*)d_in[1];
    const float* w_attn = (const float*)d_in[2];
    const float* b_attn = (const float*)d_in[3];
    const float* w_proj = (const float*)d_in[4];
    const float* b_proj = (const float*)d_in[5];
    float* out = (float*)d_out;

    __half *qkv_hi, *att_hi;
    __half *xa_hi, *wa_hi, *wp_hi, *wp_lo;
    cudaGetSymbolAddress((void**)&qkv_hi, g_qkv_hi);
    cudaGetSymbolAddress((void**)&att_hi, g_att_hi);
    cudaGetSymbolAddress((void**)&xa_hi, g_xa_hi);
    cudaGetSymbolAddress((void**)&wa_hi, g_wa_hi);
    cudaGetSymbolAddress((void**)&wp_hi, g_wp_hi);
    cudaGetSymbolAddress((void**)&wp_lo, g_wp_lo);

    const int SMEM_1T = 3 * 2 * TILE_B;   // 61440
    const int SMEM_2T = 3 * 3 * TILE_B;   // 92160
    cudaFuncSetAttribute((const void*)gemm_hmma<1, 1, 8>,
                         cudaFuncAttributeMaxDynamicSharedMemorySize, SMEM_1T);
    cudaFuncSetAttribute((const void*)gemm_hmma<2, 0, 4>,
                         cudaFuncAttributeMaxDynamicSharedMemorySize, SMEM_2T);
    cudaFuncSetAttribute((const void*)attn_hmma,
                         cudaFuncAttributeMaxDynamicSharedMemorySize, ATT_SMEM);

    // 1) all conversions in one launch
    prep_all<<<PREP_BLOCKS, 256>>>(x, xa_hi, w_attn, wa_hi,
                                   w_proj, wp_hi, wp_lo);

    // 2) qkv = xh @ Wh + b  -> f16 (1-term, 8 warps)
    gemm_hmma<1, 1, 8><<<dim3(3072 / 128, BT_ROWS / 128), 256, SMEM_1T>>>(
        xa_hi, wa_hi, nullptr, b_attn, nullptr, qkv_hi, 3072, 1024);

    // 3) attention (KV tile 128) -> att hi
    attn_hmma<<<dim3(T_SEQ / 128, 16, 2), 256, ATT_SMEM>>>(
        qkv_hi, mask, att_hi);

    // 4) out = ah @ (Wph + Wpl) + b  (fp32 out, 2-term, 4 warps)
    gemm_hmma<2, 0, 4><<<dim3(1024 / 128, BT_ROWS / 128), 128, SMEM_2T>>>(
        att_hi, wp_hi, wp_lo, b_proj, out, nullptr, 1024, 1024);
}

// round 17
// speedup vs baseline: 1.0670x; 1.0670x over previous
#include <cuda_runtime.h>
#include <cuda_fp16.h>
#include <cstdint>

#define T_SEQ 2048
#define D_MODEL 1024
#define BT_ROWS 4096            // B*T

// ---------------------------------------------------------------------------
// Scratch (device globals; no allocations anywhere).
// ---------------------------------------------------------------------------
__device__ __half g_qkv_hi[(size_t)BT_ROWS * 3072];
__device__ __half g_att_hi[(size_t)BT_ROWS * 1024];
__device__ __half g_xa_hi[(size_t)BT_ROWS * 1024];
__device__ __half g_wa_hi[(size_t)3072 * 1024];  // w_attn^T [N,K]
__device__ __half g_wp_hi[(size_t)1024 * 1024];  // w_proj^T [N,K]
__device__ __half g_wp_lo[(size_t)1024 * 1024];

// ---------------------------------------------------------------------------
// Helpers (plain sm_80-era PTX only)
// ---------------------------------------------------------------------------
__device__ __forceinline__ uint32_t smem_u32(const void* p) {
    uint32_t a;
    asm("{ .reg .u64 t; cvta.to.shared.u64 t, %1; cvt.u32.u64 %0, t; }"
        : "=r"(a) : "l"(p));
    return a;
}

__device__ __forceinline__ void cpa16(uint32_t s, const void* g) {
    asm volatile("cp.async.cg.shared.global [%0], [%1], 16;" :: "r"(s), "l"(g));
}

__device__ __forceinline__ void ldsm4(uint32_t* r, uint32_t a) {
    asm volatile("ldmatrix.sync.aligned.m8n8.x4.shared.b16 {%0,%1,%2,%3}, [%4];"
                 : "=r"(r[0]), "=r"(r[1]), "=r"(r[2]), "=r"(r[3]) : "r"(a));
}

__device__ __forceinline__ void ldsm4t(uint32_t* r, uint32_t a) {
    asm volatile("ldmatrix.sync.aligned.m8n8.x4.trans.shared.b16 {%0,%1,%2,%3}, [%4];"
                 : "=r"(r[0]), "=r"(r[1]), "=r"(r[2]), "=r"(r[3]) : "r"(a));
}

// f16 x f16 -> f32 accumulate
__device__ __forceinline__ void mma_f32(float* d, const uint32_t* a,
                                        const uint32_t* b) {
    asm volatile(
        "mma.sync.aligned.m16n8k16.row.col.f32.f16.f16.f32 "
        "{%0,%1,%2,%3}, {%4,%5,%6,%7}, {%8,%9}, {%0,%1,%2,%3};"
        : "+f"(d[0]), "+f"(d[1]), "+f"(d[2]), "+f"(d[3])
        : "r"(a[0]), "r"(a[1]), "r"(a[2]), "r"(a[3]), "r"(b[0]), "r"(b[1]));
}

// f16 x f16 -> f16 accumulate (GEMM lo cross-term)
__device__ __forceinline__ void mma_f16(uint32_t* d, const uint32_t* a,
                                        const uint32_t* b) {
    asm volatile(
        "mma.sync.aligned.m16n8k16.row.col.f16.f16.f16.f16 "
        "{%0,%1}, {%2,%3,%4,%5}, {%6,%7}, {%0,%1};"
        : "+r"(d[0]), "+r"(d[1])
        : "r"(a[0]), "r"(a[1]), "r"(a[2]), "r"(a[3]), "r"(b[0]), "r"(b[1]));
}

// pack a pair of fp32 -> f16x2 (single rounding)
__device__ __forceinline__ uint32_t pack2(float a, float b) {
    __half2 h;
    h.x = __float2half(a);
    h.y = __float2half(b);
    return *(uint32_t*)&h;
}

// ---------------------------------------------------------------------------
// Fused preparation kernel (identical to R15).
// ---------------------------------------------------------------------------
#define PREP_X_BLOCKS    (BT_ROWS * D_MODEL / 4 / 256)   // 4096
#define PREP_WA_BLOCKS   ((3072 / 32) * (1024 / 32))     // 3072
#define PREP_WP_BLOCKS   ((1024 / 32) * (1024 / 32))     // 1024
#define PREP_BLOCKS      (PREP_X_BLOCKS + PREP_WA_BLOCKS + PREP_WP_BLOCKS)

__global__ __launch_bounds__(256) void prep_all(
    const float* __restrict__ x,      __half* __restrict__ xa,
    const float* __restrict__ wa,     __half* __restrict__ wah,
    const float* __restrict__ wp,     __half* __restrict__ wph,
    __half* __restrict__ wpl)
{
    __shared__ float t[32][33];
    const int bid = blockIdx.x, tid = threadIdx.x;

    if (bid < PREP_X_BLOCKS) {
        int i = (bid * 256 + tid) * 4;
        float4 v = *(const float4*)(x + i);
        ((uint32_t*)(xa + i))[0] = pack2(v.x, v.y);
        ((uint32_t*)(xa + i))[1] = pack2(v.z, v.w);
        return;
    }

    const int tx = tid & 31, ty = tid >> 5;

    if (bid < PREP_X_BLOCKS + PREP_WA_BLOCKS) {
        const int bb = bid - PREP_X_BLOCKS;
        const int n0 = (bb % (3072 / 32)) * 32;
        const int k0 = (bb / (3072 / 32)) * 32;
#pragma unroll
        for (int j = 0; j < 32; j += 8)
            t[ty + j][tx] = wa[(size_t)(k0 + ty + j) * 3072 + n0 + tx];
        __syncthreads();
#pragma unroll
        for (int j = 0; j < 32; j += 8)
            wah[(size_t)(n0 + ty + j) * 1024 + k0 + tx] =
                __float2half(t[tx][ty + j]);
        return;
    }

    {
        const int bb = bid - PREP_X_BLOCKS - PREP_WA_BLOCKS;
        const int n0 = (bb % (1024 / 32)) * 32;
        const int k0 = (bb / (1024 / 32)) * 32;
#pragma unroll
        for (int j = 0; j < 32; j += 8)
            t[ty + j][tx] = wp[(size_t)(k0 + ty + j) * 1024 + n0 + tx];
        __syncthreads();
#pragma unroll
        for (int j = 0; j < 32; j += 8) {
            float v = t[tx][ty + j];
            __half h = __float2half(v);
            size_t o = (size_t)(n0 + ty + j) * 1024 + k0 + tx;
            wph[o] = h;
            wpl[o] = __float2half(v - __half2float(h));
        }
    }
}

// ---------------------------------------------------------------------------
// HMMA GEMM: C = Ah @ (Bh [+ Bl])^T + bias   (identical to R15)
// ---------------------------------------------------------------------------
#define GBK 32
#define ROWB 80
#define TILE_B (128 * ROWB)

template <int TERMS, int CVT_OUT, int NWARP>
__global__ __launch_bounds__(NWARP * 32) void gemm_hmma(
    const __half* __restrict__ Ahi,
    const __half* __restrict__ Bhi, const __half* __restrict__ Blo,
    const float* __restrict__ bias, float* __restrict__ C,
    __half* __restrict__ Chi,
    int N, int K)
{
    constexpr uint32_t STAGE = (1 + TERMS) * TILE_B;
    constexpr int NT = NWARP * 32;
    constexpr int MI = (NWARP == 4) ? 4 : 2;

    extern __shared__ char smc[];
    const uint32_t sb = smem_u32(smc);
    const int tid = threadIdx.x, lane = tid & 31, wid = tid >> 5;
    const int bm = blockIdx.y * 128, bn = blockIdx.x * 128;
    const int mbw = (NWARP == 4) ? (wid & 1) * 64 : (wid & 3) * 32;
    const int nbw = (NWARP == 4) ? (wid >> 1) * 64 : (wid >> 2) * 64;

    float acc[MI][8][4];
    uint32_t accL[MI][8][2];
#pragma unroll
    for (int m = 0; m < MI; m++)
#pragma unroll
        for (int n = 0; n < 8; n++) {
#pragma unroll
            for (int j = 0; j < 4; j++) acc[m][n][j] = 0.f;
            accL[m][n][0] = 0u; accL[m][n][1] = 0u;
        }

    const uint32_t aoff =
        (uint32_t)(mbw + (lane & 15)) * ROWB + (uint32_t)(lane >> 4) * 16;
    const uint32_t boff =
        (uint32_t)(nbw + (lane >> 4) * 8 + (lane & 7)) * ROWB +
        (uint32_t)((lane >> 3) & 1) * 16;

    auto load_stage = [&](int s, int kt) {
        const uint32_t st = sb + s * STAGE;
        const int kc = kt * GBK;
        const __half* gp[3] = {Ahi, Bhi, Blo};
#pragma unroll
        for (int c = 0; c < (1 + TERMS) * 512 / NT; c++) {
            int idx = tid + c * NT;
            int tile = idx >> 9;
            int rem = idx & 511;
            int row = rem >> 2, q = rem & 3;
            const int rbase = (tile == 0) ? bm : bn;
            const __half* g =
                gp[tile] + (size_t)(rbase + row) * K + kc + q * 8;
            cpa16(st + tile * TILE_B + row * ROWB + q * 16, g);
        }
        asm volatile("cp.async.commit_group;" ::: "memory");
    };

    const int KT = K / GBK;
    load_stage(0, 0);
    load_stage(1, 1);

    for (int kt = 0; kt < KT; kt++) {
        const int s = kt % 3;
        if (kt + 1 < KT)
            asm volatile("cp.async.wait_group 1;" ::: "memory");
        else
            asm volatile("cp.async.wait_group 0;" ::: "memory");
        __syncthreads();

        if (kt + 2 < KT) load_stage((kt + 2) % 3, kt + 2);

        const uint32_t st = sb + s * STAGE;
        const uint32_t stAh = st;
        const uint32_t stBh = st + TILE_B, stBl = st + 2 * TILE_B;

#pragma unroll
        for (int ks = 0; ks < 2; ks++) {
            const uint32_t ko = ks * 32;
            uint32_t bh[4][4], ah[MI][4];
#pragma unroll
            for (int p = 0; p < 4; p++)
                ldsm4(bh[p], stBh + boff + p * 16 * ROWB + ko);
#pragma unroll
            for (int m = 0; m < MI; m++)
                ldsm4(ah[m], stAh + aoff + m * 16 * ROWB + ko);
#pragma unroll
            for (int n = 0; n < 8; n++)
#pragma unroll
                for (int m = 0; m < MI; m++)
                    mma_f32(acc[m][n], ah[m], &bh[n >> 1][(n & 1) * 2]);
            if (TERMS == 2) {
                uint32_t bl[4][4];
#pragma unroll
                for (int p = 0; p < 4; p++)
                    ldsm4(bl[p], stBl + boff + p * 16 * ROWB + ko);
#pragma unroll
                for (int n = 0; n < 8; n++)
#pragma unroll
                    for (int m = 0; m < MI; m++)
                        mma_f16(accL[m][n], ah[m], &bl[n >> 1][(n & 1) * 2]);
            }
        }
    }

    // Epilogue
    const int rql = lane >> 2, cql = (lane & 3) * 2;
#pragma unroll
    for (int m = 0; m < MI; m++) {
        const int row = bm + mbw + m * 16 + rql;
#pragma unroll
        for (int n = 0; n < 8; n++) {
            const int col = bn + nbw + n * 8 + cql;
            const float bx = bias[col], by = bias[col + 1];
            float v0 = acc[m][n][0] + bx;
            float v1 = acc[m][n][1] + by;
            float v2 = acc[m][n][2] + bx;
            float v3 = acc[m][n][3] + by;
            if (TERMS == 2) {
                __half2 lo0 = *(__half2*)&accL[m][n][0];
                __half2 lo1 = *(__half2*)&accL[m][n][1];
                v0 += __half2float(lo0.x);
                v1 += __half2float(lo0.y);
                v2 += __half2float(lo1.x);
                v3 += __half2float(lo1.y);
            }
            if (CVT_OUT) {
                *(uint32_t*)(Chi + (size_t)row * N + col) = pack2(v0, v1);
                *(uint32_t*)(Chi + (size_t)(row + 8) * N + col) = pack2(v2, v3);
            } else {
                *(float2*)(C + (size_t)row * N + col) = make_float2(v0, v1);
                *(float2*)(C + (size_t)(row + 8) * N + col) = make_float2(v2, v3);
            }
        }
    }
}

// ---------------------------------------------------------------------------
// HMMA flash attention, KV tile 64 (R15 geometry), 4-stage early-issue
// pipeline (loader runs 3 tiles ahead), hoisted Q fragments.
//   S = Qh*Kh ;  O += P16 * Vh   (f32 accum)
// Smem: Q 18432 + 4 x (2*9216 + 256) = 93184.
// ---------------------------------------------------------------------------
#define AROW 144
#define ATT_QBYTES (128 * AROW)          // 18432
#define ATT_KVTILE (64 * AROW)           // 9216
#define ATT_STAGE (2 * ATT_KVTILE + 256) // 18688
#define ATT_SMEM (ATT_QBYTES + 4 * ATT_STAGE)   // 93184

__global__ __launch_bounds__(256) void attn_hmma(
    const __half* __restrict__ qkv_hi,
    const float* __restrict__ mask,
    __half* __restrict__ out_hi)
{
    extern __shared__ char smc[];
    const uint32_t sb = smem_u32(smc);
    const int tid = threadIdx.x, lane = tid & 31, w = tid >> 5;
    const int qt = blockIdx.x * 128;
    const int h = blockIdx.y, b = blockIdx.z;

    // ---- Q load (hi only), committed with kv0 ----
#pragma unroll
    for (int i = 0; i < 4; i++) {
        int idx = tid + i * 256;
        int row = idx >> 3, c = idx & 7;
        const __half* g = qkv_hi +
            (size_t)(b * T_SEQ + qt + row) * 3072 + h * 64 + c * 8;
        cpa16(sb + row * AROW + c * 16, g);
    }

    const uint32_t stg0 = sb + ATT_QBYTES;

    auto load_kv = [&](int s, int kt) {
        const uint32_t st = stg0 + s * ATT_STAGE;
#pragma unroll
        for (int i = 0; i < 4; i++) {
            int idx = tid + i * 256;
            int tile = idx >> 9;
            int rem = idx & 511;
            int row = rem >> 3, c = rem & 7;
            int coff = ((tile == 0) ? 1024 : 2048) + h * 64;
            const __half* g = qkv_hi +
                (size_t)(b * T_SEQ + kt * 64 + row) * 3072 + coff + c * 8;
            cpa16(st + tile * ATT_KVTILE + row * AROW + c * 16, g);
        }
        if (tid < 16)
            cpa16(st + 2 * ATT_KVTILE + tid * 16,
                  mask + (size_t)b * T_SEQ + kt * 64 + tid * 4);
        asm volatile("cp.async.commit_group;" ::: "memory");
    };

    load_kv(0, 0);    // group: Q + kv0
    load_kv(1, 1);
    load_kv(2, 2);

    const uint32_t aoffQ = (uint32_t)(w * 16 + (lane & 15)) * AROW +
                           (uint32_t)(lane >> 4) * 16;
    const uint32_t boffK = (uint32_t)((lane >> 4) * 8 + (lane & 7)) * AROW +
                           (uint32_t)((lane >> 3) & 1) * 16;
    const uint32_t voffV = (uint32_t)(lane & 15) * AROW +
                           (uint32_t)(lane >> 4) * 16;

    uint32_t qf[4][4];
    float mst0 = -1e30f, mst1 = -1e30f, lst0 = 0.f, lst1 = 0.f;
    float O[8][4];
#pragma unroll
    for (int n = 0; n < 8; n++)
#pragma unroll
        for (int j = 0; j < 4; j++) O[n][j] = 0.f;

    const int NKV = T_SEQ / 64;
    for (int kt = 0; kt < NKV; kt++) {
        const int s = kt & 3;
        // wait until group kt complete: allowed pending = min(2, NKV-1-kt)
        if (kt + 2 < NKV)
            asm volatile("cp.async.wait_group 2;" ::: "memory");
        else if (kt + 1 < NKV)
            asm volatile("cp.async.wait_group 1;" ::: "memory");
        else
            asm volatile("cp.async.wait_group 0;" ::: "memory");
        __syncthreads();

        if (kt == 0) {
#pragma unroll
            for (int kg = 0; kg < 4; kg++)
                ldsm4(qf[kg], sb + aoffQ + kg * 32);
        }
        if (kt + 3 < NKV) load_kv((kt + 3) & 3, kt + 3);   // early issue

        const uint32_t st = stg0 + s * ATT_STAGE;
        const float* mskp = (const float*)(smc + ATT_QBYTES +
                                           s * ATT_STAGE + 2 * ATT_KVTILE);

        float S[8][4];
#pragma unroll
        for (int n = 0; n < 8; n++)
#pragma unroll
            for (int j = 0; j < 4; j++) S[n][j] = 0.f;

#pragma unroll
        for (int kg = 0; kg < 4; kg++) {
#pragma unroll
            for (int nb = 0; nb < 4; nb++) {
                uint32_t kh[4];
                ldsm4(kh, st + boffK + nb * 16 * AROW + kg * 32);
                mma_f32(S[2 * nb],     qf[kg], &kh[0]);
                mma_f32(S[2 * nb + 1], qf[kg], &kh[2]);
            }
        }

        float mx0 = -1e30f, mx1 = -1e30f;
#pragma unroll
        for (int n = 0; n < 8; n++) {
            float2 mk = *(const float2*)(mskp + n * 8 + (lane & 3) * 2);
            float m0 = 2.f * mk.x, m1 = 2.f * mk.y;
            S[n][0] = fmaf(S[n][0], 0.125f, m0);
            S[n][1] = fmaf(S[n][1], 0.125f, m1);
            S[n][2] = fmaf(S[n][2], 0.125f, m0);
            S[n][3] = fmaf(S[n][3], 0.125f, m1);
            mx0 = fmaxf(mx0, fmaxf(S[n][0], S[n][1]));
            mx1 = fmaxf(mx1, fmaxf(S[n][2], S[n][3]));
        }
        mx0 = fmaxf(mx0, __shfl_xor_sync(0xffffffffu, mx0, 1));
        mx0 = fmaxf(mx0, __shfl_xor_sync(0xffffffffu, mx0, 2));
        mx1 = fmaxf(mx1, __shfl_xor_sync(0xffffffffu, mx1, 1));
        mx1 = fmaxf(mx1, __shfl_xor_sync(0xffffffffu, mx1, 2));

        const float mn0 = fmaxf(mst0, mx0), mn1 = fmaxf(mst1, mx1);
        const float cr0 = __expf(mst0 - mn0), cr1 = __expf(mst1 - mn1);
        mst0 = mn0; mst1 = mn1;

        float rs0 = 0.f, rs1 = 0.f;
#pragma unroll
        for (int n = 0; n < 8; n++) {
            S[n][0] = __expf(S[n][0] - mn0);
            S[n][1] = __expf(S[n][1] - mn0);
            S[n][2] = __expf(S[n][2] - mn1);
            S[n][3] = __expf(S[n][3] - mn1);
            rs0 += S[n][0] + S[n][1];
            rs1 += S[n][2] + S[n][3];
        }
        rs0 += __shfl_xor_sync(0xffffffffu, rs0, 1);
        rs0 += __shfl_xor_sync(0xffffffffu, rs0, 2);
        rs1 += __shfl_xor_sync(0xffffffffu, rs1, 1);
        rs1 += __shfl_xor_sync(0xffffffffu, rs1, 2);
        lst0 = lst0 * cr0 + rs0;
        lst1 = lst1 * cr1 + rs1;

#pragma unroll
        for (int n = 0; n < 8; n++) {
            O[n][0] *= cr0; O[n][1] *= cr0;
            O[n][2] *= cr1; O[n][3] *= cr1;
        }

#pragma unroll
        for (int kg = 0; kg < 4; kg++) {
            uint32_t ph[4];
            ph[0] = pack2(S[2 * kg][0],     S[2 * kg][1]);
            ph[1] = pack2(S[2 * kg][2],     S[2 * kg][3]);
            ph[2] = pack2(S[2 * kg + 1][0], S[2 * kg + 1][1]);
            ph[3] = pack2(S[2 * kg + 1][2], S[2 * kg + 1][3]);
#pragma unroll
            for (int nb = 0; nb < 4; nb++) {
                uint32_t vh[4];
                ldsm4t(vh, st + ATT_KVTILE + voffV + kg * 16 * AROW + nb * 32);
                mma_f32(O[2 * nb],     ph, &vh[0]);
                mma_f32(O[2 * nb + 1], ph, &vh[2]);
            }
        }
    }

    const float inv0 = 1.f / lst0, inv1 = 1.f / lst1;
    const int row0 = b * T_SEQ + qt + w * 16 + (lane >> 2);
    const int colb = h * 64 + (lane & 3) * 2;
#pragma unroll
    for (int n = 0; n < 8; n++) {
        const size_t o0 = (size_t)row0 * D_MODEL + colb + n * 8;
        const size_t o1 = (size_t)(row0 + 8) * D_MODEL + colb + n * 8;
        *(uint32_t*)(out_hi + o0) = pack2(O[n][0] * inv0, O[n][1] * inv0);
        *(uint32_t*)(out_hi + o1) = pack2(O[n][2] * inv1, O[n][3] * inv1);
    }
}

// ---------------------------------------------------------------------------
extern "C" void kernel_launch(void* const* d_in, const int* in_sizes, int n_in,
                              void* d_out, int out_size)
{
    const float* x      = (const float*)d_in[0];
    const float* mask   = (const float*)d_in[1];
    const float* w_attn = (const float*)d_in[2];
    const float* b_attn = (const float*)d_in[3];
    const float* w_proj = (const float*)d_in[4];
    const float* b_proj = (const float*)d_in[5];
    float* out = (float*)d_out;

    __half *qkv_hi, *att_hi;
    __half *xa_hi, *wa_hi, *wp_hi, *wp_lo;
    cudaGetSymbolAddress((void**)&qkv_hi, g_qkv_hi);
    cudaGetSymbolAddress((void**)&att_hi, g_att_hi);
    cudaGetSymbolAddress((void**)&xa_hi, g_xa_hi);
    cudaGetSymbolAddress((void**)&wa_hi, g_wa_hi);
    cudaGetSymbolAddress((void**)&wp_hi, g_wp_hi);
    cudaGetSymbolAddress((void**)&wp_lo, g_wp_lo);

    const int SMEM_1T = 3 * 2 * TILE_B;   // 61440
    const int SMEM_2T = 3 * 3 * TILE_B;   // 92160
    cudaFuncSetAttribute((const void*)gemm_hmma<1, 1, 8>,
                         cudaFuncAttributeMaxDynamicSharedMemorySize, SMEM_1T);
    cudaFuncSetAttribute((const void*)gemm_hmma<2, 0, 4>,
                         cudaFuncAttributeMaxDynamicSharedMemorySize, SMEM_2T);
    cudaFuncSetAttribute((const void*)attn_hmma,
                         cudaFuncAttributeMaxDynamicSharedMemorySize, ATT_SMEM);

    // 1) all conversions in one launch
    prep_all<<<PREP_BLOCKS, 256>>>(x, xa_hi, w_attn, wa_hi,
                                   w_proj, wp_hi, wp_lo);

    // 2) qkv = xh @ Wh + b  -> f16 (1-term, 8 warps)
    gemm_hmma<1, 1, 8><<<dim3(3072 / 128, BT_ROWS / 128), 256, SMEM_1T>>>(
        xa_hi, wa_hi, nullptr, b_attn, nullptr, qkv_hi, 3072, 1024);

    // 3) attention (KV tile 64, 4-stage pipeline) -> att hi
    attn_hmma<<<dim3(T_SEQ / 128, 16, 2), 256, ATT_SMEM>>>(
        qkv_hi, mask, att_hi);

    // 4) out = ah @ (Wph + Wpl) + b  (fp32 out, 2-term, 4 warps)
    gemm_hmma<2, 0, 4><<<dim3(1024 / 128, BT_ROWS / 128), 128, SMEM_2T>>>(
        att_hi, wp_hi, wp_lo, b_proj, out, nullptr, 1024, 1024);
}